// round 4
// baseline (speedup 1.0000x reference)
#include <cuda_runtime.h>
#include <cstdint>
#include <cstddef>

#define B_ 4
#define S_ 4096
#define D_ 768
#define ATTN_SCALE 0.03608439182435161f   // 1/sqrt(768)

// ---------------- scratch (device globals: allocation-free rule) -----------
__device__ float g_xr[(size_t)B_ * S_ * D_];      // tf32-rounded x
__device__ float g_Wr[3ull * D_ * D_];            // tf32-rounded Wq|Wk|Wv
__device__ float g_Q [(size_t)B_ * S_ * D_];
__device__ float g_K [(size_t)B_ * S_ * D_];
__device__ float g_Vt[(size_t)B_ * D_ * S_];      // V transposed: [b][e][s]
__device__ float g_P [(size_t)B_ * S_ * S_];      // unnormalized exp(scores), tf32-rounded
__device__ float g_rowsum[B_ * S_];

// ---------------- helpers ----------------------------------------------------
static __device__ __forceinline__ float rna(float x){
    float r; asm("cvt.rna.tf32.f32 %0, %1;" : "=f"(r) : "f"(x)); return r;
}

static __device__ __forceinline__ uint32_t smem_u32(const void* p){
    uint32_t a;
    asm("{ .reg .u64 t; cvta.to.shared.u64 t, %1; cvt.u32.u64 %0, t; }" : "=r"(a) : "l"(p));
    return a;
}

static __device__ __forceinline__ void cp16(uint32_t sa, const void* g){
    asm volatile("cp.async.ca.shared.global [%0], [%1], 16;" :: "r"(sa), "l"(g));
}
#define CP_COMMIT() asm volatile("cp.async.commit_group;" ::: "memory")
#define CP_WAIT2()  asm volatile("cp.async.wait_group 2;"  ::: "memory")

// stage: A[128][36] then B[256][36] floats (pad 36 => conflict-free frag LDS)
#define BOFF  4608                    // 128*36 floats
#define SSTG  13824                   // (128+256)*36 floats per stage
#define SMEM_BYTES (4 * SSTG * 4)     // 4 stages = 221184 B

static __device__ __forceinline__ void stage_load(uint32_t sbase,
        const float* __restrict__ A, const float* __restrict__ Bm,
        int rsA, int rsB, int tid){
    #pragma unroll
    for (int i = 0; i < 2; i++){                  // A: 1024 x 16B
        const int idx = tid + 512*i;
        const int r = idx >> 3, c = (idx & 7) * 4;
        cp16(sbase + (uint32_t)(r*36 + c)*4u, A + (size_t)r*rsA + c);
    }
    #pragma unroll
    for (int i = 0; i < 4; i++){                  // B: 2048 x 16B
        const int idx = tid + 512*i;
        const int r = idx >> 3, c = (idx & 7) * 4;
        cp16(sbase + (uint32_t)(BOFF + r*36 + c)*4u, Bm + (size_t)r*rsB + c);
    }
}

static __device__ __forceinline__ void mma8(float* d, const uint32_t* a, const uint32_t* b){
    asm volatile("mma.sync.aligned.m16n8k8.row.col.f32.tf32.tf32.f32 "
        "{%0,%1,%2,%3}, {%4,%5,%6,%7}, {%8,%9}, {%0,%1,%2,%3};"
        : "+f"(d[0]), "+f"(d[1]), "+f"(d[2]), "+f"(d[3])
        : "r"(a[0]), "r"(a[1]), "r"(a[2]), "r"(a[3]), "r"(b[0]), "r"(b[1]));
}

// warp tile 32(m) x 64(n), k-chunk 32 (4 ksteps of 8); 16 warps = 4m x 4n
static __device__ __forceinline__ void compute_chunk(float acc[2][8][4],
        const float* __restrict__ st, int WM, int WN, int lane){
    const float* sA = st;
    const float* sB = st + BOFF;
    #pragma unroll
    for (int s = 0; s < 4; s++){
        const int ac = 8*s + (lane & 3);
        uint32_t a[2][4], b[8][2];
        #pragma unroll
        for (int f = 0; f < 2; f++){
            const float* p = sA + (WM + 16*f + (lane >> 2))*36 + ac;
            a[f][0] = __float_as_uint(p[0]);
            a[f][1] = __float_as_uint(p[8*36]);
            a[f][2] = __float_as_uint(p[4]);
            a[f][3] = __float_as_uint(p[8*36 + 4]);
        }
        #pragma unroll
        for (int g = 0; g < 8; g++){
            const float* p = sB + (WN + 8*g + (lane >> 2))*36 + ac;
            b[g][0] = __float_as_uint(p[0]);
            b[g][1] = __float_as_uint(p[4]);
        }
        #pragma unroll
        for (int f = 0; f < 2; f++)
            #pragma unroll
            for (int g = 0; g < 8; g++)
                mma8(acc[f][g], a[f], b[g]);
    }
}

// 4-stage cp.async software pipeline over nch k-chunks of 32
static __device__ __forceinline__ void gemm_pipeline(float acc[2][8][4], float* smf,
        const float* __restrict__ A, const float* __restrict__ Bm,
        int rsA, int rsB, int nch, int tid, int WM, int WN, int lane){
    const uint32_t sb = smem_u32(smf);
    #pragma unroll
    for (int p = 0; p < 3; p++){
        if (p < nch) stage_load(sb + (uint32_t)(p*SSTG*4), A + p*32, Bm + p*32, rsA, rsB, tid);
        CP_COMMIT();
    }
    #pragma unroll 1
    for (int ch = 0; ch < nch; ch++){
        CP_WAIT2();
        __syncthreads();
        const int nx = ch + 3;
        if (nx < nch)
            stage_load(sb + (uint32_t)((nx & 3)*SSTG*4), A + nx*32, Bm + nx*32, rsA, rsB, tid);
        CP_COMMIT();
        compute_chunk(acc, smf + (ch & 3)*SSTG, WM, WN, lane);
    }
}

#define ACC_INIT(acc) \
    _Pragma("unroll") for (int f_ = 0; f_ < 2; f_++) \
    _Pragma("unroll") for (int g_ = 0; g_ < 8; g_++) \
    _Pragma("unroll") for (int j_ = 0; j_ < 4; j_++) acc[f_][g_][j_] = 0.0f;

// ---------------- tiny kernels ----------------------------------------------
__global__ void k_zero(){ g_rowsum[blockIdx.x * 1024 + threadIdx.x] = 0.0f; }

__global__ void k_round_x(const float* __restrict__ x){
    const int i = blockIdx.x * 256 + threadIdx.x;            // n4 = 3145728
    const float4 v = reinterpret_cast<const float4*>(x)[i];
    reinterpret_cast<float4*>(g_xr)[i] = make_float4(rna(v.x), rna(v.y), rna(v.z), rna(v.w));
}

__global__ void k_round_w(const float* __restrict__ Wq, const float* __restrict__ Wk,
                          const float* __restrict__ Wv){
    const int sel = blockIdx.y;
    const float* src = sel == 0 ? Wq : (sel == 1 ? Wk : Wv);
    const int i = blockIdx.x * 256 + threadIdx.x;            // n4 = 147456
    const float4 v = reinterpret_cast<const float4*>(src)[i];
    reinterpret_cast<float4*>(g_Wr + (size_t)sel * D_ * D_)[i] =
        make_float4(rna(v.x), rna(v.y), rna(v.z), rna(v.w));
}

// ---------------- kernel 1: QKV projection ----------------------------------
// grid(128 row-tiles, 9 = {Wq,Wk,Wv} x 3 col-tiles of 256)
__global__ void __launch_bounds__(512,1)
k_qkv(){
    extern __shared__ float smf[];
    const int tid = threadIdx.x, lane = tid & 31, wid = tid >> 5;
    const int WM = (wid & 3) * 32, WN = (wid >> 2) * 64;
    const int rt = blockIdx.x;
    const int wsel = blockIdx.y / 3, ct = blockIdx.y % 3;

    const float* A  = g_xr + (size_t)rt * 128 * D_;
    const float* Bm = g_Wr + (size_t)wsel * D_ * D_ + (size_t)ct * 256 * D_;

    float acc[2][8][4];
    ACC_INIT(acc);
    gemm_pipeline(acc, smf, A, Bm, D_, D_, 24, tid, WM, WN, lane);

    if (wsel < 2){
        float* dst = (wsel == 0 ? g_Q : g_K) + (size_t)rt * 128 * D_ + ct * 256;
        #pragma unroll
        for (int f = 0; f < 2; f++){
            const int m0 = WM + 16*f + (lane >> 2);
            #pragma unroll
            for (int g = 0; g < 8; g++){
                const int n0 = WN + 8*g + 2*(lane & 3);
                *reinterpret_cast<float2*>(dst + (size_t)m0*D_ + n0) =
                    make_float2(rna(acc[f][g][0]), rna(acc[f][g][1]));
                *reinterpret_cast<float2*>(dst + (size_t)(m0+8)*D_ + n0) =
                    make_float2(rna(acc[f][g][2]), rna(acc[f][g][3]));
            }
        }
    } else {
        // V: transpose through smem, write coalesced columns of g_Vt
        __syncthreads();
        float* sT = smf;                      // [256 n][stride 132 m]
        #pragma unroll
        for (int f = 0; f < 2; f++){
            const int m0 = WM + 16*f + (lane >> 2);
            #pragma unroll
            for (int g = 0; g < 8; g++){
                const int n0 = WN + 8*g + 2*(lane & 3);
                sT[(n0  )*132 + m0    ] = rna(acc[f][g][0]);
                sT[(n0+1)*132 + m0    ] = rna(acc[f][g][1]);
                sT[(n0  )*132 + m0 + 8] = rna(acc[f][g][2]);
                sT[(n0+1)*132 + m0 + 8] = rna(acc[f][g][3]);
            }
        }
        __syncthreads();
        const int b = (rt * 128) >> 12;
        const int srow = (rt * 128) & 4095;
        const int e = tid >> 1, h = (tid & 1) * 64;
        float* dst = g_Vt + ((size_t)b*D_ + ct*256 + e) * S_ + srow + h;
        const float* src = sT + e*132 + h;
        #pragma unroll
        for (int i = 0; i < 16; i++)
            *reinterpret_cast<float4*>(dst + 4*i) = *reinterpret_cast<const float4*>(src + 4*i);
    }
}

// ---------------- kernel 2: causal scores -> unnormalized exp ---------------
// grid(272 causal (qt:128, kt:256) tile-pairs, 4 batches)
__global__ void __launch_bounds__(512,1)
k_scores(){
    extern __shared__ float smf[];
    const int tid = threadIdx.x, lane = tid & 31, wid = tid >> 5;
    const int WM = (wid & 3) * 32, WN = (wid >> 2) * 64;
    const int b = blockIdx.y;
    const int p = blockIdx.x;
    int qt = 0, c = 0;
    for (;;){ const int w = (qt >> 1) + 1; if (c + w > p) break; c += w; qt++; }
    const int kt = p - c;   // 256-wide k-tile index

    const float* A  = g_Q + ((size_t)b*S_ + qt*128) * D_;
    const float* Bm = g_K + ((size_t)b*S_ + kt*256) * D_;

    float acc[2][8][4];
    ACC_INIT(acc);
    gemm_pipeline(acc, smf, A, Bm, D_, D_, 24, tid, WM, WN, lane);

    __syncthreads();                 // before smem reuse for rowsum
    float* rs = smf;
    if (tid < 128) rs[tid] = 0.0f;
    __syncthreads();

    float* Pb = g_P + ((size_t)b*S_ + qt*128) * S_ + kt*256;

    #pragma unroll
    for (int f = 0; f < 2; f++){
        const int m0 = WM + 16*f + (lane >> 2);
        const int qg0 = qt*128 + m0, qg1 = qg0 + 8;
        float s0 = 0.0f, s1 = 0.0f;
        #pragma unroll
        for (int g = 0; g < 8; g++){
            const int n0 = WN + 8*g + 2*(lane & 3);
            const int kg = kt*256 + n0;
            float e00 = (kg     <= qg0) ? rna(__expf(acc[f][g][0] * ATTN_SCALE)) : 0.0f;
            float e01 = (kg + 1 <= qg0) ? rna(__expf(acc[f][g][1] * ATTN_SCALE)) : 0.0f;
            float e10 = (kg     <= qg1) ? rna(__expf(acc[f][g][2] * ATTN_SCALE)) : 0.0f;
            float e11 = (kg + 1 <= qg1) ? rna(__expf(acc[f][g][3] * ATTN_SCALE)) : 0.0f;
            s0 += e00 + e01; s1 += e10 + e11;
            *reinterpret_cast<float2*>(Pb + (size_t)m0*S_ + n0)     = make_float2(e00, e01);
            *reinterpret_cast<float2*>(Pb + (size_t)(m0+8)*S_ + n0) = make_float2(e10, e11);
        }
        s0 += __shfl_xor_sync(0xffffffffu, s0, 1);
        s0 += __shfl_xor_sync(0xffffffffu, s0, 2);
        s1 += __shfl_xor_sync(0xffffffffu, s1, 1);
        s1 += __shfl_xor_sync(0xffffffffu, s1, 2);
        if ((lane & 3) == 0){
            atomicAdd(&rs[m0],     s0);
            atomicAdd(&rs[m0 + 8], s1);
        }
    }
    __syncthreads();
    if (tid < 128) atomicAdd(&g_rowsum[b*S_ + qt*128 + tid], rs[tid]);
}

// ---------------- kernel 3: O = (P @ Vt^T) / rowsum --------------------------
// 1D grid of 384, work-sorted heavy-qt-first: (qt desc, e-tile of 256, batch)
__global__ void __launch_bounds__(512,1)
k_pv(float* __restrict__ out){
    extern __shared__ float smf[];
    const int tid = threadIdx.x, lane = tid & 31, wid = tid >> 5;
    const int WM = (wid & 3) * 32, WN = (wid >> 2) * 64;
    const int bid = blockIdx.x;
    const int qt = 31 - bid / 12;
    const int sub = bid % 12;
    const int ex = sub % 3, b = sub / 3;

    const float* A  = g_P  + ((size_t)b*S_ + qt*128) * S_;
    const float* Bm = g_Vt + ((size_t)b*D_ + ex*256) * S_;
    const int nch = (qt + 1) * 4;

    float acc[2][8][4];
    ACC_INIT(acc);
    gemm_pipeline(acc, smf, A, Bm, S_, S_, nch, tid, WM, WN, lane);

    #pragma unroll
    for (int f = 0; f < 2; f++){
        const int m0 = WM + 16*f + (lane >> 2);
        const float inv0 = 1.0f / g_rowsum[b*S_ + qt*128 + m0];
        const float inv1 = 1.0f / g_rowsum[b*S_ + qt*128 + m0 + 8];
        float* dst0 = out + ((size_t)b*S_ + qt*128 + m0    ) * D_ + ex*256;
        float* dst1 = out + ((size_t)b*S_ + qt*128 + m0 + 8) * D_ + ex*256;
        #pragma unroll
        for (int g = 0; g < 8; g++){
            const int n0 = WN + 8*g + 2*(lane & 3);
            *reinterpret_cast<float2*>(dst0 + n0) =
                make_float2(acc[f][g][0]*inv0, acc[f][g][1]*inv0);
            *reinterpret_cast<float2*>(dst1 + n0) =
                make_float2(acc[f][g][2]*inv1, acc[f][g][3]*inv1);
        }
    }
}

// ---------------- launcher ---------------------------------------------------
extern "C" void kernel_launch(void* const* d_in, const int* in_sizes, int n_in,
                              void* d_out, int out_size)
{
    (void)in_sizes; (void)n_in; (void)out_size;
    const float* x  = (const float*)d_in[0];
    const float* Wq = (const float*)d_in[1];
    const float* Wk = (const float*)d_in[2];
    const float* Wv = (const float*)d_in[3];
    float* out = (float*)d_out;

    cudaFuncSetAttribute(k_qkv,    cudaFuncAttributeMaxDynamicSharedMemorySize, SMEM_BYTES);
    cudaFuncSetAttribute(k_scores, cudaFuncAttributeMaxDynamicSharedMemorySize, SMEM_BYTES);
    cudaFuncSetAttribute(k_pv,     cudaFuncAttributeMaxDynamicSharedMemorySize, SMEM_BYTES);

    k_zero   <<<16, 1024>>>();
    k_round_x<<<12288, 256>>>(x);
    k_round_w<<<dim3(576, 3), 256>>>(Wq, Wk, Wv);
    k_qkv    <<<dim3(128, 9), 512, SMEM_BYTES>>>();
    k_scores <<<dim3(272, 4), 512, SMEM_BYTES>>>();
    k_pv     <<<384, 512, SMEM_BYTES>>>(out);
}

// round 5
// speedup vs baseline: 1.0792x; 1.0792x over previous
#include <cuda_runtime.h>
#include <cstdint>
#include <cstddef>

#define B_ 4
#define S_ 4096
#define D_ 768
#define ATTN_SCALE 0.03608439182435161f   // 1/sqrt(768)

// ---------------- scratch (device globals: allocation-free rule) -----------
__device__ float g_xr[(size_t)B_ * S_ * D_];      // tf32-rounded x
__device__ float g_Wr[3ull * D_ * D_];            // tf32-rounded Wq|Wk|Wv
__device__ float g_Q [(size_t)B_ * S_ * D_];
__device__ float g_K [(size_t)B_ * S_ * D_];
__device__ float g_Vt[(size_t)B_ * D_ * S_];      // V transposed: [b][e][s]
__device__ float g_P [(size_t)B_ * S_ * S_];      // unnormalized exp(scores), tf32-rounded
__device__ float g_rowsum[B_ * S_];

// ---------------- helpers ----------------------------------------------------
static __device__ __forceinline__ float rna(float x){
    float r; asm("cvt.rna.tf32.f32 %0, %1;" : "=f"(r) : "f"(x)); return r;
}

static __device__ __forceinline__ uint32_t smem_u32(const void* p){
    uint32_t a;
    asm("{ .reg .u64 t; cvta.to.shared.u64 t, %1; cvt.u32.u64 %0, t; }" : "=r"(a) : "l"(p));
    return a;
}

static __device__ __forceinline__ void cp16(uint32_t sa, const void* g){
    asm volatile("cp.async.ca.shared.global [%0], [%1], 16;" :: "r"(sa), "l"(g));
}
#define CP_COMMIT() asm volatile("cp.async.commit_group;" ::: "memory")
#define CP_WAIT1()  asm volatile("cp.async.wait_group 1;"  ::: "memory")

// stage layout: A[128][36] floats then B[128][36] floats (pad 36 => conflict-free frag LDS)
#define SSTG  9216          // floats per stage
#define BOFF  4608          // B offset in floats
#define SMEM_BYTES (3 * SSTG * 4)   // 110592 B -> 2 CTAs/SM

static __device__ __forceinline__ void stage_load(uint32_t sbase,
        const float* __restrict__ A, const float* __restrict__ Bm,
        int rsA, int rsB, int tid){
    #pragma unroll
    for (int i = 0; i < 4; i++){
        const int idx = tid + 256*i;          // 1024 x 16B per operand
        const int r = idx >> 3, c = (idx & 7) * 4;
        cp16(sbase + (uint32_t)(r*36 + c)*4u,          A  + (size_t)r*rsA + c);
        cp16(sbase + (uint32_t)(BOFF + r*36 + c)*4u,   Bm + (size_t)r*rsB + c);
    }
}

static __device__ __forceinline__ void mma8(float* d, const uint32_t* a, const uint32_t* b){
    asm volatile("mma.sync.aligned.m16n8k8.row.col.f32.tf32.tf32.f32 "
        "{%0,%1,%2,%3}, {%4,%5,%6,%7}, {%8,%9}, {%0,%1,%2,%3};"
        : "+f"(d[0]), "+f"(d[1]), "+f"(d[2]), "+f"(d[3])
        : "r"(a[0]), "r"(a[1]), "r"(a[2]), "r"(a[3]), "r"(b[0]), "r"(b[1]));
}

// warp tile 64(m) x 32(n), k-chunk 32 (4 ksteps of 8); 8 warps = 2m x 4n
static __device__ __forceinline__ void compute_chunk(float acc[4][4][4],
        const float* __restrict__ st, int WM, int WN, int lane){
    const float* sA = st;
    const float* sB = st + BOFF;
    #pragma unroll
    for (int s = 0; s < 4; s++){
        const int ac = 8*s + (lane & 3);
        uint32_t a[4][4], b[4][2];
        #pragma unroll
        for (int f = 0; f < 4; f++){
            const float* p = sA + (WM + 16*f + (lane >> 2))*36 + ac;
            a[f][0] = __float_as_uint(p[0]);
            a[f][1] = __float_as_uint(p[8*36]);
            a[f][2] = __float_as_uint(p[4]);
            a[f][3] = __float_as_uint(p[8*36 + 4]);
        }
        #pragma unroll
        for (int g = 0; g < 4; g++){
            const float* p = sB + (WN + 8*g + (lane >> 2))*36 + ac;
            b[g][0] = __float_as_uint(p[0]);
            b[g][1] = __float_as_uint(p[4]);
        }
        #pragma unroll
        for (int f = 0; f < 4; f++)
            #pragma unroll
            for (int g = 0; g < 4; g++)
                mma8(acc[f][g], a[f], b[g]);
    }
}

// 3-stage cp.async software pipeline over nch k-chunks of 32
static __device__ __forceinline__ void gemm_pipeline(float acc[4][4][4], float* smf,
        const float* __restrict__ A, const float* __restrict__ Bm,
        int rsA, int rsB, int nch, int tid, int WM, int WN, int lane){
    const uint32_t sb = smem_u32(smf);
    #pragma unroll
    for (int p = 0; p < 2; p++){
        if (p < nch) stage_load(sb + (uint32_t)(p*SSTG*4), A + p*32, Bm + p*32, rsA, rsB, tid);
        CP_COMMIT();
    }
    int cur = 0, nxt = 2;       // buffer indices mod 3
    #pragma unroll 1
    for (int ch = 0; ch < nch; ch++){
        CP_WAIT1();
        __syncthreads();
        const int nx = ch + 2;
        if (nx < nch)
            stage_load(sb + (uint32_t)(nxt*SSTG*4), A + nx*32, Bm + nx*32, rsA, rsB, tid);
        CP_COMMIT();
        compute_chunk(acc, smf + cur*SSTG, WM, WN, lane);
        cur = (cur == 2) ? 0 : cur + 1;
        nxt = (nxt == 2) ? 0 : nxt + 1;
    }
}

#define ACC_INIT(acc) \
    _Pragma("unroll") for (int f_ = 0; f_ < 4; f_++) \
    _Pragma("unroll") for (int g_ = 0; g_ < 4; g_++) \
    _Pragma("unroll") for (int j_ = 0; j_ < 4; j_++) acc[f_][g_][j_] = 0.0f;

// ---------------- tiny kernels ----------------------------------------------
__global__ void k_zero(){ g_rowsum[blockIdx.x * 1024 + threadIdx.x] = 0.0f; }

__global__ void k_round_x(const float* __restrict__ x){
    const int i = blockIdx.x * 256 + threadIdx.x;            // n4 = 3145728
    const float4 v = reinterpret_cast<const float4*>(x)[i];
    reinterpret_cast<float4*>(g_xr)[i] = make_float4(rna(v.x), rna(v.y), rna(v.z), rna(v.w));
}

__global__ void k_round_w(const float* __restrict__ Wq, const float* __restrict__ Wk,
                          const float* __restrict__ Wv){
    const int sel = blockIdx.y;
    const float* src = sel == 0 ? Wq : (sel == 1 ? Wk : Wv);
    const int i = blockIdx.x * 256 + threadIdx.x;            // n4 = 147456
    const float4 v = reinterpret_cast<const float4*>(src)[i];
    reinterpret_cast<float4*>(g_Wr + (size_t)sel * D_ * D_)[i] =
        make_float4(rna(v.x), rna(v.y), rna(v.z), rna(v.w));
}

// ---------------- kernel 1: QKV projection ----------------------------------
// grid(128 row-tiles, 18 = {Wq,Wk,Wv} x 6 col-tiles)
__global__ void __launch_bounds__(256,2)
k_qkv(){
    extern __shared__ float smf[];
    const int tid = threadIdx.x, lane = tid & 31, wid = tid >> 5;
    const int WM = (wid & 1) * 64, WN = (wid >> 1) * 32;
    const int rt = blockIdx.x;
    const int wsel = blockIdx.y / 6, ct = blockIdx.y % 6;

    const float* A  = g_xr + (size_t)rt * 128 * D_;
    const float* Bm = g_Wr + (size_t)wsel * D_ * D_ + (size_t)ct * 128 * D_;

    float acc[4][4][4];
    ACC_INIT(acc);
    gemm_pipeline(acc, smf, A, Bm, D_, D_, 24, tid, WM, WN, lane);

    if (wsel < 2){
        float* dst = (wsel == 0 ? g_Q : g_K) + (size_t)rt * 128 * D_ + ct * 128;
        #pragma unroll
        for (int f = 0; f < 4; f++){
            const int m0 = WM + 16*f + (lane >> 2);
            #pragma unroll
            for (int g = 0; g < 4; g++){
                const int n0 = WN + 8*g + 2*(lane & 3);
                *reinterpret_cast<float2*>(dst + (size_t)m0*D_ + n0) =
                    make_float2(rna(acc[f][g][0]), rna(acc[f][g][1]));
                *reinterpret_cast<float2*>(dst + (size_t)(m0+8)*D_ + n0) =
                    make_float2(rna(acc[f][g][2]), rna(acc[f][g][3]));
            }
        }
    } else {
        // V: transpose through smem, write coalesced columns of g_Vt
        __syncthreads();
        float* sT = smf;                      // [128 n][stride 132 m]
        #pragma unroll
        for (int f = 0; f < 4; f++){
            const int m0 = WM + 16*f + (lane >> 2);
            #pragma unroll
            for (int g = 0; g < 4; g++){
                const int n0 = WN + 8*g + 2*(lane & 3);
                sT[(n0  )*132 + m0    ] = rna(acc[f][g][0]);
                sT[(n0+1)*132 + m0    ] = rna(acc[f][g][1]);
                sT[(n0  )*132 + m0 + 8] = rna(acc[f][g][2]);
                sT[(n0+1)*132 + m0 + 8] = rna(acc[f][g][3]);
            }
        }
        __syncthreads();
        const int b = (rt * 128) >> 12;
        const int srow = (rt * 128) & 4095;
        const int e = tid >> 1, h = (tid & 1) * 64;
        float* dst = g_Vt + ((size_t)b*D_ + ct*128 + e) * S_ + srow + h;
        const float* src = sT + e*132 + h;
        #pragma unroll
        for (int i = 0; i < 16; i++)
            *reinterpret_cast<float4*>(dst + 4*i) = *reinterpret_cast<const float4*>(src + 4*i);
    }
}

// ---------------- kernel 2: causal scores -> unnormalized exp ---------------
// grid(528 causal tile-pairs, 4 batches)
__global__ void __launch_bounds__(256,2)
k_scores(){
    extern __shared__ float smf[];
    const int tid = threadIdx.x, lane = tid & 31, wid = tid >> 5;
    const int WM = (wid & 1) * 64, WN = (wid >> 1) * 32;
    const int b = blockIdx.y;
    const int p = blockIdx.x;
    int qt = (int)((sqrtf(8.0f*(float)p + 1.0f) - 1.0f) * 0.5f);
    while ((qt+1)*(qt+2)/2 <= p) qt++;
    while (qt*(qt+1)/2 > p) qt--;
    const int kt = p - qt*(qt+1)/2;

    const float* A  = g_Q + ((size_t)b*S_ + qt*128) * D_;
    const float* Bm = g_K + ((size_t)b*S_ + kt*128) * D_;

    float acc[4][4][4];
    ACC_INIT(acc);
    gemm_pipeline(acc, smf, A, Bm, D_, D_, 24, tid, WM, WN, lane);

    float* Pb = g_P + ((size_t)b*S_ + qt*128) * S_ + kt*128;
    const bool diag = (kt == qt);

    #pragma unroll
    for (int f = 0; f < 4; f++){
        const int m0 = WM + 16*f + (lane >> 2);
        float s0 = 0.0f, s1 = 0.0f;
        #pragma unroll
        for (int g = 0; g < 4; g++){
            const int n0 = WN + 8*g + 2*(lane & 3);
            float e00 = __expf(acc[f][g][0] * ATTN_SCALE);
            float e01 = __expf(acc[f][g][1] * ATTN_SCALE);
            float e10 = __expf(acc[f][g][2] * ATTN_SCALE);
            float e11 = __expf(acc[f][g][3] * ATTN_SCALE);
            if (diag){
                if (n0     > m0    ) e00 = 0.0f;
                if (n0 + 1 > m0    ) e01 = 0.0f;
                if (n0     > m0 + 8) e10 = 0.0f;
                if (n0 + 1 > m0 + 8) e11 = 0.0f;
            }
            e00 = rna(e00); e01 = rna(e01); e10 = rna(e10); e11 = rna(e11);
            s0 += e00 + e01; s1 += e10 + e11;
            *reinterpret_cast<float2*>(Pb + (size_t)m0*S_ + n0)     = make_float2(e00, e01);
            *reinterpret_cast<float2*>(Pb + (size_t)(m0+8)*S_ + n0) = make_float2(e10, e11);
        }
        s0 += __shfl_xor_sync(0xffffffffu, s0, 1);
        s0 += __shfl_xor_sync(0xffffffffu, s0, 2);
        s1 += __shfl_xor_sync(0xffffffffu, s1, 1);
        s1 += __shfl_xor_sync(0xffffffffu, s1, 2);
        if ((lane & 3) == 0){
            atomicAdd(&g_rowsum[b*S_ + qt*128 + m0],     s0);
            atomicAdd(&g_rowsum[b*S_ + qt*128 + m0 + 8], s1);
        }
    }
}

// ---------------- kernel 3: O = (P @ Vt^T) / rowsum --------------------------
// 1D grid of 768: qt-descending outer, (b, e-tile) inner -> co-resident CTAs
// of one qt share the P row-block in L2.
__global__ void __launch_bounds__(256,2)
k_pv(float* __restrict__ out){
    extern __shared__ float smf[];
    const int tid = threadIdx.x, lane = tid & 31, wid = tid >> 5;
    const int WM = (wid & 1) * 64, WN = (wid >> 1) * 32;
    const int bid = blockIdx.x;
    const int qt = 31 - bid / 24;
    const int sub = bid % 24;
    const int b = sub / 6, ex = sub % 6;

    const float* A  = g_P  + ((size_t)b*S_ + qt*128) * S_;
    const float* Bm = g_Vt + ((size_t)b*D_ + ex*128) * S_;
    const int nch = (qt + 1) * 4;

    float acc[4][4][4];
    ACC_INIT(acc);
    gemm_pipeline(acc, smf, A, Bm, S_, S_, nch, tid, WM, WN, lane);

    #pragma unroll
    for (int f = 0; f < 4; f++){
        const int m0 = WM + 16*f + (lane >> 2);
        const float inv0 = 1.0f / g_rowsum[b*S_ + qt*128 + m0];
        const float inv1 = 1.0f / g_rowsum[b*S_ + qt*128 + m0 + 8];
        float* dst0 = out + ((size_t)b*S_ + qt*128 + m0    ) * D_ + ex*128;
        float* dst1 = out + ((size_t)b*S_ + qt*128 + m0 + 8) * D_ + ex*128;
        #pragma unroll
        for (int g = 0; g < 4; g++){
            const int n0 = WN + 8*g + 2*(lane & 3);
            *reinterpret_cast<float2*>(dst0 + n0) =
                make_float2(acc[f][g][0]*inv0, acc[f][g][1]*inv0);
            *reinterpret_cast<float2*>(dst1 + n0) =
                make_float2(acc[f][g][2]*inv1, acc[f][g][3]*inv1);
        }
    }
}

// ---------------- launcher ---------------------------------------------------
extern "C" void kernel_launch(void* const* d_in, const int* in_sizes, int n_in,
                              void* d_out, int out_size)
{
    (void)in_sizes; (void)n_in; (void)out_size;
    const float* x  = (const float*)d_in[0];
    const float* Wq = (const float*)d_in[1];
    const float* Wk = (const float*)d_in[2];
    const float* Wv = (const float*)d_in[3];
    float* out = (float*)d_out;

    cudaFuncSetAttribute(k_qkv,    cudaFuncAttributeMaxDynamicSharedMemorySize, SMEM_BYTES);
    cudaFuncSetAttribute(k_scores, cudaFuncAttributeMaxDynamicSharedMemorySize, SMEM_BYTES);
    cudaFuncSetAttribute(k_pv,     cudaFuncAttributeMaxDynamicSharedMemorySize, SMEM_BYTES);

    k_zero   <<<16, 1024>>>();
    k_round_x<<<12288, 256>>>(x);
    k_round_w<<<dim3(576, 3), 256>>>(Wq, Wk, Wv);
    k_qkv    <<<dim3(128, 18), 256, SMEM_BYTES>>>();
    k_scores <<<dim3(528, 4),  256, SMEM_BYTES>>>();
    k_pv     <<<768, 256, SMEM_BYTES>>>(out);
}

// round 6
// speedup vs baseline: 1.9450x; 1.8022x over previous
#include <cuda_runtime.h>
#include <cuda_fp16.h>
#include <cstdint>
#include <cstddef>

#define B_ 4
#define S_ 4096
#define D_ 768
#define ATTN_SCALE 0.03608439182435161f   // 1/sqrt(768)
#define EXP_SHIFT 4.0f                    // P=exp(logit-4): fp16-safe; cancels in P/rowsum

// ---------------- scratch (device globals: allocation-free rule) -----------
__device__ __half g_xh[(size_t)B_ * S_ * D_];
__device__ __half g_Wh[3ull * D_ * D_];
__device__ __half g_Qh[(size_t)B_ * S_ * D_];
__device__ __half g_Kh[(size_t)B_ * S_ * D_];
__device__ __half g_Vth[(size_t)B_ * D_ * S_];   // V transposed: [b][e][s]
__device__ __half g_Ph[(size_t)B_ * S_ * S_];    // exp(logit-4), fp16
__device__ float  g_rowsum[B_ * S_];

// ---------------- helpers ----------------------------------------------------
static __device__ __forceinline__ uint32_t smem_u32(const void* p){
    uint32_t a;
    asm("{ .reg .u64 t; cvta.to.shared.u64 t, %1; cvt.u32.u64 %0, t; }" : "=r"(a) : "l"(p));
    return a;
}

static __device__ __forceinline__ uint32_t pack2(float a, float b){
    __half2 h = __floats2half2_rn(a, b);
    return *reinterpret_cast<uint32_t*>(&h);
}

static __device__ __forceinline__ void cp16(uint32_t sa, const void* g){
    asm volatile("cp.async.ca.shared.global [%0], [%1], 16;" :: "r"(sa), "l"(g));
}
#define CP_COMMIT() asm volatile("cp.async.commit_group;" ::: "memory")
#define CP_WAIT2()  asm volatile("cp.async.wait_group 2;"  ::: "memory")

// stage (uint32 view): A[128 rows][20 u32] then B[128][20] (16 u32 = 32 fp16 data + pad 4)
// bank(20r + c) % 32 is a perfect permutation for r=0..7, c=0..3 -> conflict-free frag LDS
#define ROWU   20
#define BOFFU  2560                  // 128*20
#define SSTGU  5120                  // u32 per stage
#define SMEM_BYTES (4 * SSTGU * 4)   // 4 stages = 81920 B -> 2 CTAs/SM

static __device__ __forceinline__ void stage_load(uint32_t sbase,
        const __half* __restrict__ A, const __half* __restrict__ Bm,
        int rsA, int rsB, int tid){
    #pragma unroll
    for (int i = 0; i < 2; i++){
        const int idx = tid + 256*i;          // 512 x 16B per operand
        const int r = idx >> 2, c = idx & 3;
        cp16(sbase + (uint32_t)(r*ROWU + c*4)*4u,           A  + (size_t)r*rsA + c*8);
        cp16(sbase + (uint32_t)(BOFFU + r*ROWU + c*4)*4u,   Bm + (size_t)r*rsB + c*8);
    }
}

static __device__ __forceinline__ void mma16(float* d, const uint32_t* a, const uint32_t* b){
    asm volatile("mma.sync.aligned.m16n8k16.row.col.f32.f16.f16.f32 "
        "{%0,%1,%2,%3}, {%4,%5,%6,%7}, {%8,%9}, {%0,%1,%2,%3};"
        : "+f"(d[0]), "+f"(d[1]), "+f"(d[2]), "+f"(d[3])
        : "r"(a[0]), "r"(a[1]), "r"(a[2]), "r"(a[3]), "r"(b[0]), "r"(b[1]));
}

// warp tile 64(m) x 32(n), k-chunk 32 (2 ksteps of 16); 8 warps = 2m x 4n
static __device__ __forceinline__ void compute_chunk(float acc[4][4][4],
        const uint32_t* __restrict__ st, int WM, int WN, int lane){
    const uint32_t* sA = st;
    const uint32_t* sB = st + BOFFU;
    #pragma unroll
    for (int s = 0; s < 2; s++){
        const int c0 = s*8 + (lane & 3);
        uint32_t a[4][4], b[4][2];
        #pragma unroll
        for (int f = 0; f < 4; f++){
            const uint32_t* p = sA + (WM + 16*f + (lane >> 2))*ROWU + c0;
            a[f][0] = p[0];
            a[f][1] = p[8*ROWU];
            a[f][2] = p[4];
            a[f][3] = p[8*ROWU + 4];
        }
        #pragma unroll
        for (int g = 0; g < 4; g++){
            const uint32_t* p = sB + (WN + 8*g + (lane >> 2))*ROWU + c0;
            b[g][0] = p[0];
            b[g][1] = p[4];
        }
        #pragma unroll
        for (int f = 0; f < 4; f++)
            #pragma unroll
            for (int g = 0; g < 4; g++)
                mma16(acc[f][g], a[f], b[g]);
    }
}

// 4-stage cp.async software pipeline over nch k-chunks of 32
static __device__ __forceinline__ void gemm_pipeline(float acc[4][4][4], uint32_t* smu,
        const __half* __restrict__ A, const __half* __restrict__ Bm,
        int rsA, int rsB, int nch, int tid, int WM, int WN, int lane){
    const uint32_t sb = smem_u32(smu);
    #pragma unroll
    for (int p = 0; p < 3; p++){
        if (p < nch) stage_load(sb + (uint32_t)(p*SSTGU*4), A + p*32, Bm + p*32, rsA, rsB, tid);
        CP_COMMIT();
    }
    #pragma unroll 1
    for (int ch = 0; ch < nch; ch++){
        CP_WAIT2();
        __syncthreads();
        const int nx = ch + 3;
        if (nx < nch)
            stage_load(sb + (uint32_t)((nx & 3)*SSTGU*4), A + nx*32, Bm + nx*32, rsA, rsB, tid);
        CP_COMMIT();
        compute_chunk(acc, smu + (ch & 3)*SSTGU, WM, WN, lane);
    }
}

#define ACC_INIT(acc) \
    _Pragma("unroll") for (int f_ = 0; f_ < 4; f_++) \
    _Pragma("unroll") for (int g_ = 0; g_ < 4; g_++) \
    _Pragma("unroll") for (int j_ = 0; j_ < 4; j_++) acc[f_][g_][j_] = 0.0f;

// ---------------- tiny kernels ----------------------------------------------
__global__ void k_zero(){ g_rowsum[blockIdx.x * 1024 + threadIdx.x] = 0.0f; }

__global__ void k_cvt_x(const float* __restrict__ x){
    const size_t i = (size_t)(blockIdx.x * 256 + threadIdx.x) * 8;   // 8 floats/thread
    const float4 u = *reinterpret_cast<const float4*>(x + i);
    const float4 v = *reinterpret_cast<const float4*>(x + i + 4);
    uint4 o = make_uint4(pack2(u.x,u.y), pack2(u.z,u.w), pack2(v.x,v.y), pack2(v.z,v.w));
    *reinterpret_cast<uint4*>(g_xh + i) = o;
}

__global__ void k_cvt_w(const float* __restrict__ Wq, const float* __restrict__ Wk,
                        const float* __restrict__ Wv){
    const int sel = blockIdx.y;
    const float* src = sel == 0 ? Wq : (sel == 1 ? Wk : Wv);
    const size_t i = (size_t)(blockIdx.x * 256 + threadIdx.x) * 8;
    const float4 u = *reinterpret_cast<const float4*>(src + i);
    const float4 v = *reinterpret_cast<const float4*>(src + i + 4);
    uint4 o = make_uint4(pack2(u.x,u.y), pack2(u.z,u.w), pack2(v.x,v.y), pack2(v.z,v.w));
    *reinterpret_cast<uint4*>(g_Wh + (size_t)sel * D_ * D_ + i) = o;
}

// ---------------- kernel 1: QKV projection ----------------------------------
// grid(128 row-tiles, 18 = {Wq,Wk,Wv} x 6 col-tiles)
__global__ void __launch_bounds__(256,2)
k_qkv(){
    extern __shared__ __align__(16) uint32_t smu[];
    const int tid = threadIdx.x, lane = tid & 31, wid = tid >> 5;
    const int WM = (wid & 1) * 64, WN = (wid >> 1) * 32;
    const int rt = blockIdx.x;
    const int wsel = blockIdx.y / 6, ct = blockIdx.y % 6;

    const __half* A  = g_xh + (size_t)rt * 128 * D_;
    const __half* Bm = g_Wh + (size_t)wsel * D_ * D_ + (size_t)ct * 128 * D_;

    float acc[4][4][4];
    ACC_INIT(acc);
    gemm_pipeline(acc, smu, A, Bm, D_, D_, 24, tid, WM, WN, lane);

    if (wsel < 2){
        __half* dst = (wsel == 0 ? g_Qh : g_Kh) + (size_t)rt * 128 * D_ + ct * 128;
        #pragma unroll
        for (int f = 0; f < 4; f++){
            const int m0 = WM + 16*f + (lane >> 2);
            #pragma unroll
            for (int g = 0; g < 4; g++){
                const int n0 = WN + 8*g + 2*(lane & 3);
                *reinterpret_cast<uint32_t*>(dst + (size_t)m0*D_ + n0)     = pack2(acc[f][g][0], acc[f][g][1]);
                *reinterpret_cast<uint32_t*>(dst + (size_t)(m0+8)*D_ + n0) = pack2(acc[f][g][2], acc[f][g][3]);
            }
        }
    } else {
        // V: transpose through smem (fp32), convert + write coalesced columns of g_Vth
        __syncthreads();
        float* sT = reinterpret_cast<float*>(smu);   // [128 n][stride 132 m] = 67584 B
        #pragma unroll
        for (int f = 0; f < 4; f++){
            const int m0 = WM + 16*f + (lane >> 2);
            #pragma unroll
            for (int g = 0; g < 4; g++){
                const int n0 = WN + 8*g + 2*(lane & 3);
                sT[(n0  )*132 + m0    ] = acc[f][g][0];
                sT[(n0+1)*132 + m0    ] = acc[f][g][1];
                sT[(n0  )*132 + m0 + 8] = acc[f][g][2];
                sT[(n0+1)*132 + m0 + 8] = acc[f][g][3];
            }
        }
        __syncthreads();
        const int b = (rt * 128) >> 12;
        const int srow = (rt * 128) & 4095;
        const int e = tid >> 1, h = (tid & 1) * 64;
        __half* dst = g_Vth + ((size_t)b*D_ + ct*128 + e) * S_ + srow + h;
        const float* src = sT + e*132 + h;
        #pragma unroll
        for (int i = 0; i < 8; i++){
            const float4 u = *reinterpret_cast<const float4*>(src + 8*i);
            const float4 v = *reinterpret_cast<const float4*>(src + 8*i + 4);
            uint4 o = make_uint4(pack2(u.x,u.y), pack2(u.z,u.w), pack2(v.x,v.y), pack2(v.z,v.w));
            *reinterpret_cast<uint4*>(dst + 8*i) = o;
        }
    }
}

// ---------------- kernel 2: causal scores -> fp16 exp(logit-4) ---------------
// grid(528 causal tile-pairs, 4 batches)
__global__ void __launch_bounds__(256,2)
k_scores(){
    extern __shared__ __align__(16) uint32_t smu[];
    const int tid = threadIdx.x, lane = tid & 31, wid = tid >> 5;
    const int WM = (wid & 1) * 64, WN = (wid >> 1) * 32;
    const int b = blockIdx.y;
    const int p = blockIdx.x;
    int qt = (int)((sqrtf(8.0f*(float)p + 1.0f) - 1.0f) * 0.5f);
    while ((qt+1)*(qt+2)/2 <= p) qt++;
    while (qt*(qt+1)/2 > p) qt--;
    const int kt = p - qt*(qt+1)/2;

    const __half* A  = g_Qh + ((size_t)b*S_ + qt*128) * D_;
    const __half* Bm = g_Kh + ((size_t)b*S_ + kt*128) * D_;

    float acc[4][4][4];
    ACC_INIT(acc);
    gemm_pipeline(acc, smu, A, Bm, D_, D_, 24, tid, WM, WN, lane);

    __half* Pb = g_Ph + ((size_t)b*S_ + qt*128) * S_ + kt*128;
    const bool diag = (kt == qt);

    #pragma unroll
    for (int f = 0; f < 4; f++){
        const int m0 = WM + 16*f + (lane >> 2);
        float s0 = 0.0f, s1 = 0.0f;
        #pragma unroll
        for (int g = 0; g < 4; g++){
            const int n0 = WN + 8*g + 2*(lane & 3);
            float e00 = __expf(fmaf(acc[f][g][0], ATTN_SCALE, -EXP_SHIFT));
            float e01 = __expf(fmaf(acc[f][g][1], ATTN_SCALE, -EXP_SHIFT));
            float e10 = __expf(fmaf(acc[f][g][2], ATTN_SCALE, -EXP_SHIFT));
            float e11 = __expf(fmaf(acc[f][g][3], ATTN_SCALE, -EXP_SHIFT));
            if (diag){
                if (n0     > m0    ) e00 = 0.0f;
                if (n0 + 1 > m0    ) e01 = 0.0f;
                if (n0     > m0 + 8) e10 = 0.0f;
                if (n0 + 1 > m0 + 8) e11 = 0.0f;
            }
            const __half2 h0 = __floats2half2_rn(e00, e01);
            const __half2 h1 = __floats2half2_rn(e10, e11);
            // sums use the fp16-rounded values (must match PV's operand exactly)
            s0 += __low2float(h0) + __high2float(h0);
            s1 += __low2float(h1) + __high2float(h1);
            *reinterpret_cast<__half2*>(Pb + (size_t)m0*S_ + n0)     = h0;
            *reinterpret_cast<__half2*>(Pb + (size_t)(m0+8)*S_ + n0) = h1;
        }
        s0 += __shfl_xor_sync(0xffffffffu, s0, 1);
        s0 += __shfl_xor_sync(0xffffffffu, s0, 2);
        s1 += __shfl_xor_sync(0xffffffffu, s1, 1);
        s1 += __shfl_xor_sync(0xffffffffu, s1, 2);
        if ((lane & 3) == 0){
            atomicAdd(&g_rowsum[b*S_ + qt*128 + m0],     s0);
            atomicAdd(&g_rowsum[b*S_ + qt*128 + m0 + 8], s1);
        }
    }
}

// ---------------- kernel 3: O = (P @ Vt^T) / rowsum --------------------------
// 1D grid of 768: qt-descending outer, (b, e-tile) inner
__global__ void __launch_bounds__(256,2)
k_pv(float* __restrict__ out){
    extern __shared__ __align__(16) uint32_t smu[];
    const int tid = threadIdx.x, lane = tid & 31, wid = tid >> 5;
    const int WM = (wid & 1) * 64, WN = (wid >> 1) * 32;
    const int bid = blockIdx.x;
    const int qt = 31 - bid / 24;
    const int sub = bid % 24;
    const int b = sub / 6, ex = sub % 6;

    const __half* A  = g_Ph  + ((size_t)b*S_ + qt*128) * S_;
    const __half* Bm = g_Vth + ((size_t)b*D_ + ex*128) * S_;
    const int nch = (qt + 1) * 4;

    float acc[4][4][4];
    ACC_INIT(acc);
    gemm_pipeline(acc, smu, A, Bm, S_, S_, nch, tid, WM, WN, lane);

    #pragma unroll
    for (int f = 0; f < 4; f++){
        const int m0 = WM + 16*f + (lane >> 2);
        const float inv0 = 1.0f / g_rowsum[b*S_ + qt*128 + m0];
        const float inv1 = 1.0f / g_rowsum[b*S_ + qt*128 + m0 + 8];
        float* dst0 = out + ((size_t)b*S_ + qt*128 + m0    ) * D_ + ex*128;
        float* dst1 = out + ((size_t)b*S_ + qt*128 + m0 + 8) * D_ + ex*128;
        #pragma unroll
        for (int g = 0; g < 4; g++){
            const int n0 = WN + 8*g + 2*(lane & 3);
            *reinterpret_cast<float2*>(dst0 + n0) =
                make_float2(acc[f][g][0]*inv0, acc[f][g][1]*inv0);
            *reinterpret_cast<float2*>(dst1 + n0) =
                make_float2(acc[f][g][2]*inv1, acc[f][g][3]*inv1);
        }
    }
}

// ---------------- launcher ---------------------------------------------------
extern "C" void kernel_launch(void* const* d_in, const int* in_sizes, int n_in,
                              void* d_out, int out_size)
{
    (void)in_sizes; (void)n_in; (void)out_size;
    const float* x  = (const float*)d_in[0];
    const float* Wq = (const float*)d_in[1];
    const float* Wk = (const float*)d_in[2];
    const float* Wv = (const float*)d_in[3];
    float* out = (float*)d_out;

    cudaFuncSetAttribute(k_qkv,    cudaFuncAttributeMaxDynamicSharedMemorySize, SMEM_BYTES);
    cudaFuncSetAttribute(k_scores, cudaFuncAttributeMaxDynamicSharedMemorySize, SMEM_BYTES);
    cudaFuncSetAttribute(k_pv,     cudaFuncAttributeMaxDynamicSharedMemorySize, SMEM_BYTES);

    k_zero  <<<16, 1024>>>();
    k_cvt_x <<<6144, 256>>>(x);
    k_cvt_w <<<dim3(288, 3), 256>>>(Wq, Wk, Wv);
    k_qkv   <<<dim3(128, 18), 256, SMEM_BYTES>>>();
    k_scores<<<dim3(528, 4),  256, SMEM_BYTES>>>();
    k_pv    <<<768, 256, SMEM_BYTES>>>(out);
}

// round 7
// speedup vs baseline: 2.2002x; 1.1312x over previous
#include <cuda_runtime.h>
#include <cuda_fp16.h>
#include <cstdint>
#include <cstddef>

#define B_ 4
#define S_ 4096
#define D_ 768
#define ATTN_SCALE 0.03608439182435161f   // 1/sqrt(768)
#define EXP_SHIFT 4.0f                    // P=exp(logit-4): fp16-safe; cancels in P/rowsum

// ---------------- scratch (device globals: allocation-free rule) -----------
__device__ __half g_xh[(size_t)B_ * S_ * D_];
__device__ __half g_Wh[3ull * D_ * D_];
__device__ __half g_Qh[(size_t)B_ * S_ * D_];
__device__ __half g_Kh[(size_t)B_ * S_ * D_];
__device__ __half g_Vth[(size_t)B_ * D_ * S_];   // V transposed: [b][e][s]
__device__ __half g_Ph[(size_t)B_ * S_ * S_];    // exp(logit-4), fp16
__device__ float  g_rowsum[B_ * S_];

// ---------------- helpers ----------------------------------------------------
static __device__ __forceinline__ uint32_t smem_u32(const void* p){
    uint32_t a;
    asm("{ .reg .u64 t; cvta.to.shared.u64 t, %1; cvt.u32.u64 %0, t; }" : "=r"(a) : "l"(p));
    return a;
}

static __device__ __forceinline__ uint32_t pack2(float a, float b){
    __half2 h = __floats2half2_rn(a, b);
    return *reinterpret_cast<uint32_t*>(&h);
}

static __device__ __forceinline__ void cp16(uint32_t sa, const void* g){
    asm volatile("cp.async.ca.shared.global [%0], [%1], 16;" :: "r"(sa), "l"(g));
}
#define CP_COMMIT() asm volatile("cp.async.commit_group;" ::: "memory")
#define CP_WAIT2()  asm volatile("cp.async.wait_group 2;"  ::: "memory")

// stage (uint32 view): A[128 rows][20 u32] then B[128][20] (16 u32 = 32 fp16 + pad 4)
// bank(20r + c) is a perfect permutation for r=0..7, c=0..3 -> conflict-free frag LDS
#define ROWU   20
#define BOFFU  2560                  // 128*20
#define SSTGU  5120                  // u32 per stage
#define SMEM_BYTES (4 * SSTGU * 4)   // 4 stages = 81920 B -> 2 CTAs/SM

// 128 threads: each loads 4x16B per operand per stage
static __device__ __forceinline__ void stage_load(uint32_t sbase,
        const __half* __restrict__ A, const __half* __restrict__ Bm,
        int rsA, int rsB, int tid){
    #pragma unroll
    for (int i = 0; i < 4; i++){
        const int idx = tid + 128*i;          // 512 x 16B per operand
        const int r = idx >> 2, c = idx & 3;
        cp16(sbase + (uint32_t)(r*ROWU + c*4)*4u,           A  + (size_t)r*rsA + c*8);
        cp16(sbase + (uint32_t)(BOFFU + r*ROWU + c*4)*4u,   Bm + (size_t)r*rsB + c*8);
    }
}

static __device__ __forceinline__ void mma16(float* d, const uint32_t* a, const uint32_t* b){
    asm volatile("mma.sync.aligned.m16n8k16.row.col.f32.f16.f16.f32 "
        "{%0,%1,%2,%3}, {%4,%5,%6,%7}, {%8,%9}, {%0,%1,%2,%3};"
        : "+f"(d[0]), "+f"(d[1]), "+f"(d[2]), "+f"(d[3])
        : "r"(a[0]), "r"(a[1]), "r"(a[2]), "r"(a[3]), "r"(b[0]), "r"(b[1]));
}

// warp tile 64(m) x 64(n), k-chunk 32 (2 ksteps of 16); 4 warps = 2m x 2n
static __device__ __forceinline__ void compute_chunk(float acc[4][8][4],
        const uint32_t* __restrict__ st, int WM, int WN, int lane){
    const uint32_t* sA = st;
    const uint32_t* sB = st + BOFFU;
    #pragma unroll
    for (int s = 0; s < 2; s++){
        const int c0 = s*8 + (lane & 3);
        uint32_t a[4][4], b[8][2];
        #pragma unroll
        for (int f = 0; f < 4; f++){
            const uint32_t* p = sA + (WM + 16*f + (lane >> 2))*ROWU + c0;
            a[f][0] = p[0];
            a[f][1] = p[8*ROWU];
            a[f][2] = p[4];
            a[f][3] = p[8*ROWU + 4];
        }
        #pragma unroll
        for (int g = 0; g < 8; g++){
            const uint32_t* p = sB + (WN + 8*g + (lane >> 2))*ROWU + c0;
            b[g][0] = p[0];
            b[g][1] = p[4];
        }
        #pragma unroll
        for (int f = 0; f < 4; f++)
            #pragma unroll
            for (int g = 0; g < 8; g++)
                mma16(acc[f][g], a[f], b[g]);
    }
}

// 4-stage cp.async software pipeline over nch k-chunks of 32
static __device__ __forceinline__ void gemm_pipeline(float acc[4][8][4], uint32_t* smu,
        const __half* __restrict__ A, const __half* __restrict__ Bm,
        int rsA, int rsB, int nch, int tid, int WM, int WN, int lane){
    const uint32_t sb = smem_u32(smu);
    #pragma unroll
    for (int p = 0; p < 3; p++){
        if (p < nch) stage_load(sb + (uint32_t)(p*SSTGU*4), A + p*32, Bm + p*32, rsA, rsB, tid);
        CP_COMMIT();
    }
    #pragma unroll 1
    for (int ch = 0; ch < nch; ch++){
        CP_WAIT2();
        __syncthreads();
        const int nx = ch + 3;
        if (nx < nch)
            stage_load(sb + (uint32_t)((nx & 3)*SSTGU*4), A + nx*32, Bm + nx*32, rsA, rsB, tid);
        CP_COMMIT();
        compute_chunk(acc, smu + (ch & 3)*SSTGU, WM, WN, lane);
    }
}

#define ACC_INIT(acc) \
    _Pragma("unroll") for (int f_ = 0; f_ < 4; f_++) \
    _Pragma("unroll") for (int g_ = 0; g_ < 8; g_++) \
    _Pragma("unroll") for (int j_ = 0; j_ < 4; j_++) acc[f_][g_][j_] = 0.0f;

// ---------------- tiny kernels ----------------------------------------------
__global__ void k_zero(){ g_rowsum[blockIdx.x * 1024 + threadIdx.x] = 0.0f; }

__global__ void k_cvt_x(const float* __restrict__ x){
    const size_t i = (size_t)(blockIdx.x * 256 + threadIdx.x) * 8;   // 8 floats/thread
    const float4 u = *reinterpret_cast<const float4*>(x + i);
    const float4 v = *reinterpret_cast<const float4*>(x + i + 4);
    uint4 o = make_uint4(pack2(u.x,u.y), pack2(u.z,u.w), pack2(v.x,v.y), pack2(v.z,v.w));
    *reinterpret_cast<uint4*>(g_xh + i) = o;
}

__global__ void k_cvt_w(const float* __restrict__ Wq, const float* __restrict__ Wk,
                        const float* __restrict__ Wv){
    const int sel = blockIdx.y;
    const float* src = sel == 0 ? Wq : (sel == 1 ? Wk : Wv);
    const size_t i = (size_t)(blockIdx.x * 256 + threadIdx.x) * 8;
    const float4 u = *reinterpret_cast<const float4*>(src + i);
    const float4 v = *reinterpret_cast<const float4*>(src + i + 4);
    uint4 o = make_uint4(pack2(u.x,u.y), pack2(u.z,u.w), pack2(v.x,v.y), pack2(v.z,v.w));
    *reinterpret_cast<uint4*>(g_Wh + (size_t)sel * D_ * D_ + i) = o;
}

// ---------------- kernel 1: QKV projection ----------------------------------
// grid(128 row-tiles, 18 = {Wq,Wk,Wv} x 6 col-tiles); 128 threads, 4 warps 64x64
__global__ void __launch_bounds__(128,2)
k_qkv(){
    extern __shared__ __align__(16) uint32_t smu[];
    const int tid = threadIdx.x, lane = tid & 31, wid = tid >> 5;
    const int WM = (wid & 1) * 64, WN = (wid >> 1) * 64;
    const int rt = blockIdx.x;
    const int wsel = blockIdx.y / 6, ct = blockIdx.y % 6;

    const __half* A  = g_xh + (size_t)rt * 128 * D_;
    const __half* Bm = g_Wh + (size_t)wsel * D_ * D_ + (size_t)ct * 128 * D_;

    float acc[4][8][4];
    ACC_INIT(acc);
    gemm_pipeline(acc, smu, A, Bm, D_, D_, 24, tid, WM, WN, lane);

    if (wsel < 2){
        __half* dst = (wsel == 0 ? g_Qh : g_Kh) + (size_t)rt * 128 * D_ + ct * 128;
        #pragma unroll
        for (int f = 0; f < 4; f++){
            const int m0 = WM + 16*f + (lane >> 2);
            #pragma unroll
            for (int g = 0; g < 8; g++){
                const int n0 = WN + 8*g + 2*(lane & 3);
                *reinterpret_cast<uint32_t*>(dst + (size_t)m0*D_ + n0)     = pack2(acc[f][g][0], acc[f][g][1]);
                *reinterpret_cast<uint32_t*>(dst + (size_t)(m0+8)*D_ + n0) = pack2(acc[f][g][2], acc[f][g][3]);
            }
        }
    } else {
        // V: transpose through smem (fp32), convert + write coalesced columns of g_Vth
        __syncthreads();
        float* sT = reinterpret_cast<float*>(smu);   // [128 n][stride 132 m] = 67584 B
        #pragma unroll
        for (int f = 0; f < 4; f++){
            const int m0 = WM + 16*f + (lane >> 2);
            #pragma unroll
            for (int g = 0; g < 8; g++){
                const int n0 = WN + 8*g + 2*(lane & 3);
                sT[(n0  )*132 + m0    ] = acc[f][g][0];
                sT[(n0+1)*132 + m0    ] = acc[f][g][1];
                sT[(n0  )*132 + m0 + 8] = acc[f][g][2];
                sT[(n0+1)*132 + m0 + 8] = acc[f][g][3];
            }
        }
        __syncthreads();
        const int b = (rt * 128) >> 12;
        const int srow = (rt * 128) & 4095;
        const int e = tid;                            // 128 e-cols
        __half* dst = g_Vth + ((size_t)b*D_ + ct*128 + e) * S_ + srow;
        const float* src = sT + e*132;
        #pragma unroll
        for (int i = 0; i < 16; i++){
            const float4 u = *reinterpret_cast<const float4*>(src + 8*i);
            const float4 v = *reinterpret_cast<const float4*>(src + 8*i + 4);
            uint4 o = make_uint4(pack2(u.x,u.y), pack2(u.z,u.w), pack2(v.x,v.y), pack2(v.z,v.w));
            *reinterpret_cast<uint4*>(dst + 8*i) = o;
        }
    }
}

// ---------------- kernel 2: causal scores -> fp16 exp(logit-4) ---------------
// grid(528 causal tile-pairs, 4 batches)
__global__ void __launch_bounds__(128,2)
k_scores(){
    extern __shared__ __align__(16) uint32_t smu[];
    const int tid = threadIdx.x, lane = tid & 31, wid = tid >> 5;
    const int WM = (wid & 1) * 64, WN = (wid >> 1) * 64;
    const int b = blockIdx.y;
    const int p = blockIdx.x;
    int qt = (int)((sqrtf(8.0f*(float)p + 1.0f) - 1.0f) * 0.5f);
    while ((qt+1)*(qt+2)/2 <= p) qt++;
    while (qt*(qt+1)/2 > p) qt--;
    const int kt = p - qt*(qt+1)/2;

    const __half* A  = g_Qh + ((size_t)b*S_ + qt*128) * D_;
    const __half* Bm = g_Kh + ((size_t)b*S_ + kt*128) * D_;

    float acc[4][8][4];
    ACC_INIT(acc);
    gemm_pipeline(acc, smu, A, Bm, D_, D_, 24, tid, WM, WN, lane);

    __half* Pb = g_Ph + ((size_t)b*S_ + qt*128) * S_ + kt*128;
    const bool diag = (kt == qt);

    #pragma unroll
    for (int f = 0; f < 4; f++){
        const int m0 = WM + 16*f + (lane >> 2);
        float s0 = 0.0f, s1 = 0.0f;
        #pragma unroll
        for (int g = 0; g < 8; g++){
            const int n0 = WN + 8*g + 2*(lane & 3);
            float e00 = __expf(fmaf(acc[f][g][0], ATTN_SCALE, -EXP_SHIFT));
            float e01 = __expf(fmaf(acc[f][g][1], ATTN_SCALE, -EXP_SHIFT));
            float e10 = __expf(fmaf(acc[f][g][2], ATTN_SCALE, -EXP_SHIFT));
            float e11 = __expf(fmaf(acc[f][g][3], ATTN_SCALE, -EXP_SHIFT));
            if (diag){
                if (n0     > m0    ) e00 = 0.0f;
                if (n0 + 1 > m0    ) e01 = 0.0f;
                if (n0     > m0 + 8) e10 = 0.0f;
                if (n0 + 1 > m0 + 8) e11 = 0.0f;
            }
            const __half2 h0 = __floats2half2_rn(e00, e01);
            const __half2 h1 = __floats2half2_rn(e10, e11);
            // sums use the fp16-rounded values (must match PV's operand exactly)
            s0 += __low2float(h0) + __high2float(h0);
            s1 += __low2float(h1) + __high2float(h1);
            *reinterpret_cast<__half2*>(Pb + (size_t)m0*S_ + n0)     = h0;
            *reinterpret_cast<__half2*>(Pb + (size_t)(m0+8)*S_ + n0) = h1;
        }
        s0 += __shfl_xor_sync(0xffffffffu, s0, 1);
        s0 += __shfl_xor_sync(0xffffffffu, s0, 2);
        s1 += __shfl_xor_sync(0xffffffffu, s1, 1);
        s1 += __shfl_xor_sync(0xffffffffu, s1, 2);
        if ((lane & 3) == 0){
            atomicAdd(&g_rowsum[b*S_ + qt*128 + m0],     s0);
            atomicAdd(&g_rowsum[b*S_ + qt*128 + m0 + 8], s1);
        }
    }
}

// ---------------- kernel 3: O = (P @ Vt^T) / rowsum --------------------------
// 1D grid of 768: qt-descending outer, (b, e-tile) inner
__global__ void __launch_bounds__(128,2)
k_pv(float* __restrict__ out){
    extern __shared__ __align__(16) uint32_t smu[];
    const int tid = threadIdx.x, lane = tid & 31, wid = tid >> 5;
    const int WM = (wid & 1) * 64, WN = (wid >> 1) * 64;
    const int bid = blockIdx.x;
    const int qt = 31 - bid / 24;
    const int sub = bid % 24;
    const int b = sub / 6, ex = sub % 6;

    const __half* A  = g_Ph  + ((size_t)b*S_ + qt*128) * S_;
    const __half* Bm = g_Vth + ((size_t)b*D_ + ex*128) * S_;
    const int nch = (qt + 1) * 4;

    float acc[4][8][4];
    ACC_INIT(acc);
    gemm_pipeline(acc, smu, A, Bm, S_, S_, nch, tid, WM, WN, lane);

    #pragma unroll
    for (int f = 0; f < 4; f++){
        const int m0 = WM + 16*f + (lane >> 2);
        const float inv0 = 1.0f / g_rowsum[b*S_ + qt*128 + m0];
        const float inv1 = 1.0f / g_rowsum[b*S_ + qt*128 + m0 + 8];
        float* dst0 = out + ((size_t)b*S_ + qt*128 + m0    ) * D_ + ex*128;
        float* dst1 = out + ((size_t)b*S_ + qt*128 + m0 + 8) * D_ + ex*128;
        #pragma unroll
        for (int g = 0; g < 8; g++){
            const int n0 = WN + 8*g + 2*(lane & 3);
            *reinterpret_cast<float2*>(dst0 + n0) =
                make_float2(acc[f][g][0]*inv0, acc[f][g][1]*inv0);
            *reinterpret_cast<float2*>(dst1 + n0) =
                make_float2(acc[f][g][2]*inv1, acc[f][g][3]*inv1);
        }
    }
}

// ---------------- launcher ---------------------------------------------------
extern "C" void kernel_launch(void* const* d_in, const int* in_sizes, int n_in,
                              void* d_out, int out_size)
{
    (void)in_sizes; (void)n_in; (void)out_size;
    const float* x  = (const float*)d_in[0];
    const float* Wq = (const float*)d_in[1];
    const float* Wk = (const float*)d_in[2];
    const float* Wv = (const float*)d_in[3];
    float* out = (float*)d_out;

    cudaFuncSetAttribute(k_qkv,    cudaFuncAttributeMaxDynamicSharedMemorySize, SMEM_BYTES);
    cudaFuncSetAttribute(k_scores, cudaFuncAttributeMaxDynamicSharedMemorySize, SMEM_BYTES);
    cudaFuncSetAttribute(k_pv,     cudaFuncAttributeMaxDynamicSharedMemorySize, SMEM_BYTES);

    k_zero  <<<16, 1024>>>();
    k_cvt_x <<<6144, 256>>>(x);
    k_cvt_w <<<dim3(288, 3), 256>>>(Wq, Wk, Wv);
    k_qkv   <<<dim3(128, 18), 128, SMEM_BYTES>>>();
    k_scores<<<dim3(528, 4),  128, SMEM_BYTES>>>();
    k_pv    <<<768, 128, SMEM_BYTES>>>(out);
}